// round 16
// baseline (speedup 1.0000x reference)
#include <cuda_runtime.h>
#include <cuda_bf16.h>
#include <math.h>
#include <stdint.h>

#define NN 131072
#define FN 64
#define FF 16
#define HH 128
#define EE 2097152
#define BB 256
#define LL 32

// ---------------- scratch ----------------------------------------------------
__device__ int   g_deg[NN];          // zeroed by csr_scan after use
__device__ int   g_rowptr[NN];
__device__ int   g_rowend[NN];
__device__ int   g_cursor[NN];
__device__ int   g_esrc[EE];
__device__ int   g_ctr;              // reset by escatter after use
__device__ float g_inv[NN];

__device__ __nv_bfloat16 g_xb[NN * FN];
__device__ __nv_bfloat16 g_h1b[NN * HH];

__device__ float g_agg1[NN * FN];
__device__ float g_h1[NN * HH];
__device__ float g_agg2[NN * HH];
__device__ float g_nemb[NN * HH];
__device__ float g_gsum[BB * HH];    // zeroed by lstm head section after use
__device__ float g_gcnt[BB];
__device__ float g_Xg[BB * LL * 4 * HH];
__device__ float g_WT[HH * 4 * HH];

__device__ __forceinline__ float sigf(float x) { return 1.0f / (1.0f + __expf(-x)); }

__device__ __forceinline__ uint32_t cvt_tf32(float f) {
    uint32_t r; asm("cvt.rna.tf32.f32 %0, %1;" : "=r"(r) : "f"(f)); return r;
}
__device__ __forceinline__ void mma_tf32(float4& c, const uint32_t a[4], uint32_t b0, uint32_t b1) {
    asm volatile("mma.sync.aligned.m16n8k8.row.col.f32.tf32.tf32.f32 "
                 "{%0,%1,%2,%3}, {%4,%5,%6,%7}, {%8,%9}, {%0,%1,%2,%3};"
                 : "+f"(c.x), "+f"(c.y), "+f"(c.z), "+f"(c.w)
                 : "r"(a[0]), "r"(a[1]), "r"(a[2]), "r"(a[3]), "r"(b0), "r"(b1));
}
__device__ __forceinline__ void cp16(void* smem_dst, const void* gsrc) {
    unsigned d = (unsigned)__cvta_generic_to_shared(smem_dst);
    asm volatile("cp.async.cg.shared.global [%0], [%1], 16;" :: "r"(d), "l"(gsrc) : "memory");
}
#define CP_COMMIT() asm volatile("cp.async.commit_group;" ::: "memory")
#define CP_WAIT(N)  asm volatile("cp.async.wait_group %0;" :: "n"(N) : "memory")

__device__ __forceinline__ void st_cs2(float* p, float a, float b) {
    asm volatile("st.global.cs.v2.f32 [%0], {%1,%2};" :: "l"(p), "f"(a), "f"(b) : "memory");
}
__device__ __forceinline__ void st_cs4(float* p, float4 v) {
    asm volatile("st.global.cs.v4.f32 [%0], {%1,%2,%3,%4};"
                 :: "l"(p), "f"(v.x), "f"(v.y), "f"(v.z), "f"(v.w) : "memory");
}

// ---------------- fused: x->bf16 mirror || degree count || Whh transpose ------
__global__ void xbcount_kernel(const float* __restrict__ x, const int* __restrict__ ei,
                               const float* __restrict__ Whh) {
    int bid = blockIdx.x;
    if (bid < 8192) {
        int i = bid * 256 + threadIdx.x;
        float4 v = *(const float4*)(x + (size_t)i * 4);
        __nv_bfloat162 a = __float22bfloat162_rn(make_float2(v.x, v.y));
        __nv_bfloat162 b = __float22bfloat162_rn(make_float2(v.z, v.w));
        uint2 packed = make_uint2(*reinterpret_cast<uint32_t*>(&a), *reinterpret_cast<uint32_t*>(&b));
        *(uint2*)(g_xb + (size_t)i * 4) = packed;
    } else if (bid < 16384) {
        int e = (bid - 8192) * 256 + threadIdx.x;
        atomicAdd(&g_deg[__ldg(&ei[EE + e])], 1);
    } else {
        int idx = (bid - 16384) * 256 + threadIdx.x;   // 65536
        int j = idx >> 7, k = idx & 127;
        g_WT[k * 512 + j] = Whh[idx];
    }
}

// ---------------- fused CSR scan (order-free base via atomic counter) --------
__global__ void csr_scan_kernel() {
    __shared__ int s[256];
    __shared__ int sbase;
    int t = threadIdx.x;
    int i = blockIdx.x * 256 + t;
    int d = g_deg[i];
    s[t] = d;
    __syncthreads();
    for (int off = 1; off < 256; off <<= 1) {
        int u = (t >= off) ? s[t - off] : 0;
        __syncthreads();
        s[t] += u;
        __syncthreads();
    }
    if (t == 255) sbase = atomicAdd(&g_ctr, s[255]);
    __syncthreads();
    int beg = sbase + s[t] - d;
    g_rowptr[i] = beg;
    g_rowend[i] = beg + d;
    g_cursor[i] = beg;
    g_inv[i] = 1.0f / fmaxf((float)d, 1.0f);
    g_deg[i] = 0;
}

__global__ void escatter_kernel(const int* __restrict__ ei) {
    if (blockIdx.x == 0 && threadIdx.x == 0) g_ctr = 0;
    int e = blockIdx.x * 256 + threadIdx.x;
    int src = __ldg(&ei[e]);
    int dst = __ldg(&ei[EE + e]);
    int pos = atomicAdd(&g_cursor[dst], 1);
    g_esrc[pos] = src;
}

// ---------------- aggregation (bf16 gathers via shfl'd byte-offsets) ----------
__global__ void agg1_kernel() {
    int warp = threadIdx.x >> 5, lane = threadIdx.x & 31;
    int n = blockIdx.x * 8 + warp;
    int beg = g_rowptr[n], end = g_rowend[n];
    const char* xb = (const char*)g_xb;
    int lb = lane * 4;
    float2 acc = make_float2(0.0f, 0.0f);
    for (int base = beg; base < end; base += 32) {
        int cnt = end - base; if (cnt > 32) cnt = 32;
        int myoff = (lane < cnt) ? (__ldg(&g_esrc[base + lane]) << 7) : 0;
        int j = 0;
        for (; j + 8 <= cnt; j += 8) {
            uint32_t u[8];
            #pragma unroll
            for (int k = 0; k < 8; k++)
                u[k] = *(const uint32_t*)(xb + __shfl_sync(0xffffffffu, myoff, j + k) + lb);
            #pragma unroll
            for (int k = 0; k < 8; k++) {
                acc.x += __uint_as_float(u[k] << 16);
                acc.y += __uint_as_float(u[k] & 0xFFFF0000u);
            }
        }
        for (; j + 2 <= cnt; j += 2) {
            uint32_t u0 = *(const uint32_t*)(xb + __shfl_sync(0xffffffffu, myoff, j) + lb);
            uint32_t u1 = *(const uint32_t*)(xb + __shfl_sync(0xffffffffu, myoff, j + 1) + lb);
            acc.x += __uint_as_float(u0 << 16) + __uint_as_float(u1 << 16);
            acc.y += __uint_as_float(u0 & 0xFFFF0000u) + __uint_as_float(u1 & 0xFFFF0000u);
        }
        if (j < cnt) {
            uint32_t u0 = *(const uint32_t*)(xb + __shfl_sync(0xffffffffu, myoff, j) + lb);
            acc.x += __uint_as_float(u0 << 16);
            acc.y += __uint_as_float(u0 & 0xFFFF0000u);
        }
    }
    float inv = g_inv[n];
    st_cs2(g_agg1 + (size_t)n * FN + lane * 2, acc.x * inv, acc.y * inv);
}

__global__ void agg2_kernel() {
    int warp = threadIdx.x >> 5, lane = threadIdx.x & 31;
    int n = blockIdx.x * 8 + warp;
    int beg = g_rowptr[n], end = g_rowend[n];
    const char* hb = (const char*)g_h1b;
    int lb = lane * 8;
    float4 acc = make_float4(0.0f, 0.0f, 0.0f, 0.0f);
    for (int base = beg; base < end; base += 32) {
        int cnt = end - base; if (cnt > 32) cnt = 32;
        int myoff = (lane < cnt) ? (__ldg(&g_esrc[base + lane]) << 8) : 0;
        int j = 0;
        for (; j + 4 <= cnt; j += 4) {
            uint2 u[4];
            #pragma unroll
            for (int k = 0; k < 4; k++)
                u[k] = *(const uint2*)(hb + __shfl_sync(0xffffffffu, myoff, j + k) + lb);
            #pragma unroll
            for (int k = 0; k < 4; k++) {
                acc.x += __uint_as_float(u[k].x << 16);
                acc.y += __uint_as_float(u[k].x & 0xFFFF0000u);
                acc.z += __uint_as_float(u[k].y << 16);
                acc.w += __uint_as_float(u[k].y & 0xFFFF0000u);
            }
        }
        for (; j < cnt; j++) {
            uint2 u0 = *(const uint2*)(hb + __shfl_sync(0xffffffffu, myoff, j) + lb);
            acc.x += __uint_as_float(u0.x << 16);
            acc.y += __uint_as_float(u0.x & 0xFFFF0000u);
            acc.z += __uint_as_float(u0.y << 16);
            acc.w += __uint_as_float(u0.y & 0xFFFF0000u);
        }
    }
    float inv = g_inv[n];
    acc.x *= inv; acc.y *= inv; acc.z *= inv; acc.w *= inv;
    st_cs4(g_agg2 + (size_t)n * HH + lane * 4, acc);
}

// ============= tf32 mma GEMMs, cp.async double-buffered A ====================
__global__ void __launch_bounds__(256, 1)
mmagemm1_kernel(const float* __restrict__ x, const float* __restrict__ Wl,
                const float* __restrict__ Wr, const float* __restrict__ b1) {
    extern __shared__ char smem[];
    uint32_t* sBf = (uint32_t*)smem;                       // 64KB
    uint32_t* sA0 = (uint32_t*)(smem + 65536);             // 67584B
    uint32_t* sA1 = (uint32_t*)(smem + 65536 + 67584);
    float*    sBias = (float*)(smem + 65536 + 2 * 67584);
    int t = threadIdx.x;
    int wid = t >> 5, lane = t & 31;
    int g = lane >> 2, c = lane & 3;
    int wm = wid >> 1, wn = wid & 1;
    int r0 = wm * 32, jbase = wn * 64;

    for (int i = t; i < 16 * 16 * 32; i += 256) {
        int lane_i = i & 31, nt = (i >> 5) & 15, ks = i >> 9;
        int j = nt * 8 + (lane_i >> 2);
        int k = ks * 8 + (lane_i & 3);
        const float* Wp0 = (k < 64) ? &Wl[j * 64 + k] : &Wr[j * 64 + k - 64];
        const float* Wp1 = (k + 4 < 64) ? &Wl[j * 64 + k + 4] : &Wr[j * 64 + k + 4 - 64];
        sBf[i * 2 + 0] = cvt_tf32(__ldg(Wp0));
        sBf[i * 2 + 1] = cvt_tf32(__ldg(Wp1));
    }
    if (t < 128) sBias[t] = __ldg(&b1[t]);
    __syncthreads();

    const int T = NN / 128, G = gridDim.x;
    auto issueA = [&](int tile, uint32_t* buf) {
        int row0 = tile * 128;
        #pragma unroll
        for (int i = 0; i < 16; i++) {
            int idx = t + i * 256;
            int r = idx >> 5, q = idx & 31;
            const float* src = (q < 16) ? (g_agg1 + (size_t)(row0 + r) * FN + q * 4)
                                        : (x + (size_t)(row0 + r) * FN + (q - 16) * 4);
            cp16(buf + r * 132 + q * 4, src);
        }
        CP_COMMIT();
    };

    int tile = blockIdx.x;
    if (tile < T) issueA(tile, sA0);
    int cur = 0;
    while (tile < T) {
        int nxt = tile + G;
        uint32_t* bufc = cur ? sA1 : sA0;
        uint32_t* bufn = cur ? sA0 : sA1;
        if (nxt < T) { issueA(nxt, bufn); CP_WAIT(1); } else { CP_WAIT(0); }
        __syncthreads();

        float4 acc[2][8];
        #pragma unroll
        for (int mt = 0; mt < 2; mt++)
            #pragma unroll
            for (int nt = 0; nt < 8; nt++) acc[mt][nt] = make_float4(0.f, 0.f, 0.f, 0.f);

        #pragma unroll
        for (int ks = 0; ks < 16; ks++) {
            int k0 = ks * 8;
            uint32_t a[2][4];
            #pragma unroll
            for (int mt = 0; mt < 2; mt++) {
                const uint32_t* base = bufc + (r0 + mt * 16 + g) * 132 + k0 + c;
                a[mt][0] = base[0];
                a[mt][1] = base[8 * 132];
                a[mt][2] = base[4];
                a[mt][3] = base[8 * 132 + 4];
            }
            const uint32_t* bb = sBf + ((ks * 16 + wn * 8) * 32 + lane) * 2;
            #pragma unroll
            for (int nt = 0; nt < 8; nt++) {
                uint32_t b0 = bb[nt * 64], b1 = bb[nt * 64 + 1];
                mma_tf32(acc[0][nt], a[0], b0, b1);
                mma_tf32(acc[1][nt], a[1], b0, b1);
            }
        }

        int row0 = tile * 128;
        #pragma unroll
        for (int mt = 0; mt < 2; mt++) {
            int m0 = row0 + r0 + mt * 16 + g;
            #pragma unroll
            for (int nt = 0; nt < 8; nt++) {
                int j = jbase + nt * 8 + 2 * c;
                float bx = sBias[j], by = sBias[j + 1];
                float4 ac = acc[mt][nt];
                float2 lo = make_float2(fmaxf(ac.x + bx, 0.f), fmaxf(ac.y + by, 0.f));
                float2 hi = make_float2(fmaxf(ac.z + bx, 0.f), fmaxf(ac.w + by, 0.f));
                *(float2*)(g_h1 + (size_t)m0 * HH + j) = lo;
                *(float2*)(g_h1 + (size_t)(m0 + 8) * HH + j) = hi;
                __nv_bfloat162 blo = __float22bfloat162_rn(lo);
                __nv_bfloat162 bhi = __float22bfloat162_rn(hi);
                *(__nv_bfloat162*)(g_h1b + (size_t)m0 * HH + j) = blo;
                *(__nv_bfloat162*)(g_h1b + (size_t)(m0 + 8) * HH + j) = bhi;
            }
        }
        __syncthreads();
        cur ^= 1;
        tile = nxt;
    }
}

// gemm2: 64x128 tile, K=256 as two staged halves (agg2 then h1). Pipelined.
__global__ void __launch_bounds__(256, 1)
mmagemm2_kernel(const float* __restrict__ Wl, const float* __restrict__ Wr,
                const float* __restrict__ b2) {
    extern __shared__ char smem[];
    uint32_t* sBf = (uint32_t*)smem;                         // 128KB
    uint32_t* sA0 = (uint32_t*)(smem + 131072);              // 33792B
    uint32_t* sA1 = (uint32_t*)(smem + 131072 + 33792);
    float*    sBias = (float*)(smem + 131072 + 2 * 33792);
    int t = threadIdx.x;
    int wid = t >> 5, lane = t & 31;
    int g = lane >> 2, c = lane & 3;
    int wm = wid >> 1, wn = wid & 1;
    int r0 = wm * 16, jbase = wn * 64;

    for (int i = t; i < 32 * 16 * 32; i += 256) {
        int lane_i = i & 31, nt = (i >> 5) & 15, ks = i >> 9;
        int j = nt * 8 + (lane_i >> 2);
        int k = ks * 8 + (lane_i & 3);
        const float* Wp0 = (k < 128) ? &Wl[j * 128 + k] : &Wr[j * 128 + k - 128];
        const float* Wp1 = (k + 4 < 128) ? &Wl[j * 128 + k + 4] : &Wr[j * 128 + k + 4 - 128];
        sBf[i * 2 + 0] = cvt_tf32(__ldg(Wp0));
        sBf[i * 2 + 1] = cvt_tf32(__ldg(Wp1));
    }
    if (t < 128) sBias[t] = __ldg(&b2[t]);
    __syncthreads();

    const int T = NN / 64, G = gridDim.x;
    auto issueA = [&](int tile, int kh, uint32_t* buf) {
        int row0 = tile * 64;
        const float* srcA = kh ? g_h1 : g_agg2;
        #pragma unroll
        for (int i = 0; i < 8; i++) {
            int idx = t + i * 256;
            int r = idx >> 5, q = idx & 31;
            cp16(buf + r * 132 + q * 4, srcA + (size_t)(row0 + r) * HH + q * 4);
        }
        CP_COMMIT();
    };

    int tile = blockIdx.x;
    if (tile < T) issueA(tile, 0, sA0);
    int cur = 0;
    while (tile < T) {
        float4 acc[8];
        #pragma unroll
        for (int nt = 0; nt < 8; nt++) acc[nt] = make_float4(0.f, 0.f, 0.f, 0.f);

        #pragma unroll 1
        for (int kh = 0; kh < 2; kh++) {
            uint32_t* bufc = cur ? sA1 : sA0;
            uint32_t* bufn = cur ? sA0 : sA1;
            int ntile = tile, nkh = kh + 1;
            if (nkh == 2) { ntile = tile + G; nkh = 0; }
            if (ntile < T) { issueA(ntile, nkh, bufn); CP_WAIT(1); } else { CP_WAIT(0); }
            __syncthreads();

            #pragma unroll
            for (int ks = 0; ks < 16; ks++) {
                int k0 = ks * 8;
                uint32_t a[4];
                const uint32_t* base = bufc + (r0 + g) * 132 + k0 + c;
                a[0] = base[0];
                a[1] = base[8 * 132];
                a[2] = base[4];
                a[3] = base[8 * 132 + 4];
                const uint32_t* bb = sBf + (((kh * 16 + ks) * 16 + wn * 8) * 32 + lane) * 2;
                #pragma unroll
                for (int nt = 0; nt < 8; nt++)
                    mma_tf32(acc[nt], a, bb[nt * 64], bb[nt * 64 + 1]);
            }
            __syncthreads();
            cur ^= 1;
        }

        int m0 = tile * 64 + r0 + g;
        #pragma unroll
        for (int nt = 0; nt < 8; nt++) {
            int j = jbase + nt * 8 + 2 * c;
            float bx = sBias[j], by = sBias[j + 1];
            float4 ac = acc[nt];
            *(float2*)(g_nemb + (size_t)m0 * HH + j) =
                make_float2(fmaxf(ac.x + bx, 0.f), fmaxf(ac.y + by, 0.f));
            *(float2*)(g_nemb + (size_t)(m0 + 8) * HH + j) =
                make_float2(fmaxf(ac.z + bx, 0.f), fmaxf(ac.w + by, 0.f));
        }
        tile += G;
    }
}

// ---------------- graph mean pooling -------------------------------------------
__global__ void pool_kernel(const int* __restrict__ batch) {
    int t = threadIdx.x;
    int j = t & 127, half = t >> 7;
    int n0 = blockIdx.x * 256 + half * 128;
    float sum = 0.0f, cc = 0.0f;
    int cur = __ldg(&batch[n0]);
    for (int r = 0; r < 128; r++) {
        int b = __ldg(&batch[n0 + r]);
        if (b != cur) {
            atomicAdd(&g_gsum[cur * HH + j], sum);
            if (j == 0) atomicAdd(&g_gcnt[cur], cc);
            sum = 0.0f; cc = 0.0f; cur = b;
        }
        sum += g_nemb[(size_t)(n0 + r) * HH + j];
        cc += 1.0f;
    }
    atomicAdd(&g_gsum[cur * HH + j], sum);
    if (j == 0) atomicAdd(&g_gcnt[cur], cc);
}

// ---------------- xg GEMM on tensor cores (cp.async staging) ------------------
__global__ void __launch_bounds__(256, 1)
xg_mma_kernel(const int* __restrict__ path_idx, const float* __restrict__ Wih,
              const float* __restrict__ bih, const float* __restrict__ bhh) {
    extern __shared__ char smem[];
    uint32_t* sBf = (uint32_t*)smem;
    uint32_t* sA  = (uint32_t*)(smem + 65536);
    float*    sBias = (float*)(smem + 65536 + 67584);
    __shared__ int snode[128];
    int t = threadIdx.x;
    int wid = t >> 5, lane = t & 31;
    int g = lane >> 2, c = lane & 3;
    int wm = wid >> 1, wn = wid & 1;
    int r0 = wm * 32;
    int jchunk = blockIdx.y * 128;
    int row0 = blockIdx.x * 128;

    if (t < 128) snode[t] = __ldg(&path_idx[row0 + t]);
    for (int i = t; i < 16 * 16 * 32; i += 256) {
        int lane_i = i & 31, nt = (i >> 5) & 15, ks = i >> 9;
        int j = nt * 8 + (lane_i >> 2);
        int k = ks * 8 + (lane_i & 3);
        sBf[i * 2 + 0] = cvt_tf32(__ldg(&Wih[(size_t)(jchunk + j) * 128 + k]));
        sBf[i * 2 + 1] = cvt_tf32(__ldg(&Wih[(size_t)(jchunk + j) * 128 + k + 4]));
    }
    if (t < 128) sBias[t] = __ldg(&bih[jchunk + t]) + __ldg(&bhh[jchunk + t]);
    __syncthreads();

    #pragma unroll
    for (int i = 0; i < 16; i++) {
        int idx = t + i * 256;
        int r = idx >> 5, q = idx & 31;
        cp16(sA + r * 132 + q * 4, g_nemb + (size_t)snode[r] * HH + q * 4);
    }
    CP_COMMIT();
    CP_WAIT(0);
    __syncthreads();

    float4 acc[2][8];
    #pragma unroll
    for (int mt = 0; mt < 2; mt++)
        #pragma unroll
        for (int nt = 0; nt < 8; nt++) acc[mt][nt] = make_float4(0.f, 0.f, 0.f, 0.f);

    #pragma unroll
    for (int ks = 0; ks < 16; ks++) {
        int k0 = ks * 8;
        uint32_t a[2][4];
        #pragma unroll
        for (int mt = 0; mt < 2; mt++) {
            const uint32_t* base = sA + (r0 + mt * 16 + g) * 132 + k0 + c;
            a[mt][0] = base[0];
            a[mt][1] = base[8 * 132];
            a[mt][2] = base[4];
            a[mt][3] = base[8 * 132 + 4];
        }
        const uint32_t* bb = sBf + ((ks * 16 + wn * 8) * 32 + lane) * 2;
        #pragma unroll
        for (int nt = 0; nt < 8; nt++) {
            uint32_t b0 = bb[nt * 64], b1 = bb[nt * 64 + 1];
            mma_tf32(acc[0][nt], a[0], b0, b1);
            mma_tf32(acc[1][nt], a[1], b0, b1);
        }
    }

    #pragma unroll
    for (int mt = 0; mt < 2; mt++) {
        int m0 = row0 + r0 + mt * 16 + g;
        #pragma unroll
        for (int nt = 0; nt < 8; nt++) {
            int jl = wn * 64 + nt * 8 + 2 * c;
            float bx = sBias[jl], by = sBias[jl + 1];
            float4 ac = acc[mt][nt];
            *(float2*)(g_Xg + (size_t)m0 * 512 + jchunk + jl) = make_float2(ac.x + bx, ac.y + by);
            *(float2*)(g_Xg + (size_t)(m0 + 8) * 512 + jchunk + jl) = make_float2(ac.z + bx, ac.w + by);
        }
    }
}

// ---------------- LSTM + fused scoring head -----------------------------------
// 128 blocks x 2 batches; 96 Whh rows in smem; head computed in-block at the end.
#define LSTM_WROWS 96
__global__ void lstm_kernel(const int* __restrict__ path_len,
                            const float* __restrict__ flow, const float* __restrict__ Wf,
                            const float* __restrict__ bf, const float* __restrict__ Ws1,
                            const float* __restrict__ bs1, const float* __restrict__ Ws2,
                            const float* __restrict__ bs2, float* __restrict__ out) {
    extern __shared__ float dyn[];
    float* sW  = dyn;
    float* sh  = dyn + LSTM_WROWS * 512;
    float* scm = sh + 256;
    float* sG  = scm + 256;              // 1024 floats, reused by head
    __shared__ int splen[2];
    int t = threadIdx.x;
    int b0 = blockIdx.x * 2;
    for (int i = t; i < LSTM_WROWS * 512 / 4; i += 128)
        *(float4*)(sW + i * 4) = *(const float4*)(g_WT + i * 4);
    for (int i = t; i < 256; i += 128) { sh[i] = 0.0f; scm[i] = 0.0f; }
    if (t < 2) splen[t] = path_len[b0 + t];
    __syncthreads();
    int jq = t;
    for (int step = 0; step < LL; step++) {
        float4 a0 = *(const float4*)(g_Xg + ((size_t)b0 * LL + step) * 512 + jq * 4);
        float4 a1 = *(const float4*)(g_Xg + ((size_t)(b0 + 1) * LL + step) * 512 + jq * 4);
        #pragma unroll 4
        for (int k = 0; k < LSTM_WROWS; k++) {
            float4 w = *(const float4*)(sW + k * 512 + jq * 4);
            float hA = sh[k], hB = sh[128 + k];
            a0.x += w.x * hA; a0.y += w.y * hA; a0.z += w.z * hA; a0.w += w.w * hA;
            a1.x += w.x * hB; a1.y += w.y * hB; a1.z += w.z * hB; a1.w += w.w * hB;
        }
        #pragma unroll 4
        for (int k = LSTM_WROWS; k < 128; k++) {
            float4 w = *(const float4*)(g_WT + k * 512 + jq * 4);
            float hA = sh[k], hB = sh[128 + k];
            a0.x += w.x * hA; a0.y += w.y * hA; a0.z += w.z * hA; a0.w += w.w * hA;
            a1.x += w.x * hB; a1.y += w.y * hB; a1.z += w.z * hB; a1.w += w.w * hB;
        }
        *(float4*)(sG + jq * 4) = a0;
        *(float4*)(sG + 512 + jq * 4) = a1;
        __syncthreads();
        #pragma unroll
        for (int u = 0; u < 2; u++) {
            int idx = t + u * 128;
            int b = idx >> 7, j = idx & 127;
            float ig = sG[b * 512 + j];
            float fg = sG[b * 512 + 128 + j];
            float gg = sG[b * 512 + 256 + j];
            float og = sG[b * 512 + 384 + j];
            float cn = sigf(fg) * scm[b * 128 + j] + sigf(ig) * tanhf(gg);
            float hn = sigf(og) * tanhf(cn);
            if (step < splen[b]) { scm[b * 128 + j] = cn; sh[b * 128 + j] = hn; }
        }
        __syncthreads();
    }

    // ---- fused head: score the two batches using sh as path_emb ----
    float* comb = sG;            // 320 floats
    float* red_ = sG + 384;      // 128 floats
    int j = t;                   // 0..127
    #pragma unroll 1
    for (int bl = 0; bl < 2; bl++) {
        int b = b0 + bl;
        comb[j] = g_gsum[b * HH + j] * (1.0f / fmaxf(g_gcnt[b], 1.0f));
        comb[128 + j] = sh[bl * 128 + j];
        if (j < 64) {
            float a = __ldg(&bf[j]);
            #pragma unroll
            for (int k = 0; k < FF; k++) a += flow[b * FF + k] * Wf[j * FF + k];
            comb[256 + j] = fmaxf(a, 0.0f);
        }
        __syncthreads();
        g_gsum[b * HH + j] = 0.0f;        // self-clean for next replay
        if (j == 0) g_gcnt[b] = 0.0f;

        float acc = __ldg(&bs1[j]);
        const float4* wr = (const float4*)(Ws1 + (size_t)j * 320);
        const float4* cb = (const float4*)comb;
        #pragma unroll 8
        for (int k = 0; k < 80; k++) {
            float4 w = wr[k], c = cb[k];
            acc += w.x * c.x + w.y * c.y + w.z * c.z + w.w * c.w;
        }
        float h = fmaxf(acc, 0.0f);
        red_[j] = h * __ldg(&Ws2[j]);
        __syncthreads();
        for (int s = 64; s > 0; s >>= 1) {
            if (j < s) red_[j] += red_[j + s];
            __syncthreads();
        }
        if (j == 0) out[b] = red_[0] + __ldg(&bs2[0]);
        __syncthreads();
    }
}

// ---------------- launch ------------------------------------------------------
extern "C" void kernel_launch(void* const* d_in, const int* in_sizes, int n_in,
                              void* d_out, int out_size) {
    const float* x        = (const float*)d_in[0];
    const int*   ei       = (const int*)d_in[1];
    const int*   batch    = (const int*)d_in[2];
    const int*   path_idx = (const int*)d_in[3];
    const int*   path_len = (const int*)d_in[4];
    const float* flow     = (const float*)d_in[5];
    const float* Wl1 = (const float*)d_in[6];
    const float* Wr1 = (const float*)d_in[7];
    const float* b1  = (const float*)d_in[8];
    const float* Wl2 = (const float*)d_in[9];
    const float* Wr2 = (const float*)d_in[10];
    const float* b2  = (const float*)d_in[11];
    const float* Wih = (const float*)d_in[12];
    const float* Whh = (const float*)d_in[13];
    const float* bih = (const float*)d_in[14];
    const float* bhh = (const float*)d_in[15];
    const float* Wf  = (const float*)d_in[16];
    const float* bf  = (const float*)d_in[17];
    const float* Ws1 = (const float*)d_in[18];
    const float* bs1 = (const float*)d_in[19];
    const float* Ws2 = (const float*)d_in[20];
    const float* bs2 = (const float*)d_in[21];
    float* out = (float*)d_out;

    const int SMG1 = 65536 + 2 * 67584 + 512;     // 201280
    const int SMG2 = 131072 + 2 * 33792 + 512;    // 199168
    const int SMXG = 65536 + 67584 + 512;         // 133632
    const int SMLSTM = (LSTM_WROWS * 512 + 256 + 256 + 1024) * 4;   // 202752
    cudaFuncSetAttribute(mmagemm1_kernel, cudaFuncAttributeMaxDynamicSharedMemorySize, SMG1);
    cudaFuncSetAttribute(mmagemm2_kernel, cudaFuncAttributeMaxDynamicSharedMemorySize, SMG2);
    cudaFuncSetAttribute(xg_mma_kernel,   cudaFuncAttributeMaxDynamicSharedMemorySize, SMXG);
    cudaFuncSetAttribute(lstm_kernel,     cudaFuncAttributeMaxDynamicSharedMemorySize, SMLSTM);

    xbcount_kernel<<<16640, 256>>>(x, ei, Whh);
    csr_scan_kernel<<<512, 256>>>();
    escatter_kernel<<<8192, 256>>>(ei);
    agg1_kernel<<<16384, 256>>>();
    mmagemm1_kernel<<<148, 256, SMG1>>>(x, Wl1, Wr1, b1);
    agg2_kernel<<<16384, 256>>>();
    mmagemm2_kernel<<<148, 256, SMG2>>>(Wl2, Wr2, b2);
    pool_kernel<<<512, 256>>>(batch);
    xg_mma_kernel<<<dim3(64, 4), 256, SMXG>>>(path_idx, Wih, bih, bhh);
    lstm_kernel<<<128, 128, SMLSTM>>>(path_len, flow, Wf, bf, Ws1, bs1, Ws2, bs2, out);
}

// round 17
// speedup vs baseline: 1.0303x; 1.0303x over previous
#include <cuda_runtime.h>
#include <cuda_bf16.h>
#include <math.h>
#include <stdint.h>

#define NN 131072
#define FN 64
#define FF 16
#define HH 128
#define EE 2097152
#define BB 256
#define LL 32

// ---------------- scratch ----------------------------------------------------
__device__ int   g_deg[NN];          // zeroed by csr_scan after use
__device__ int   g_rowptr[NN];
__device__ int   g_rowend[NN];
__device__ int   g_cursor[NN];
__device__ int   g_esrc[EE];
__device__ int   g_ctr;              // reset by escatter after use
__device__ float g_inv[NN];

__device__ __nv_bfloat16 g_xb[NN * FN];
__device__ __nv_bfloat16 g_h1b[NN * HH];   // bf16 h1 (sole copy)

__device__ float g_agg1[NN * FN];
__device__ float g_agg2[NN * HH];
__device__ float g_nemb[NN * HH];
__device__ float g_gsum[BB * HH];    // zeroed by lstm head section after use
__device__ float g_gcnt[BB];
__device__ float g_Xg[BB * LL * 4 * HH];
__device__ float g_WT[HH * 4 * HH];

__device__ __forceinline__ float sigf(float x) { return 1.0f / (1.0f + __expf(-x)); }

__device__ __forceinline__ uint32_t cvt_tf32(float f) {
    uint32_t r; asm("cvt.rna.tf32.f32 %0, %1;" : "=r"(r) : "f"(f)); return r;
}
__device__ __forceinline__ void mma_tf32(float4& c, const uint32_t a[4], uint32_t b0, uint32_t b1) {
    asm volatile("mma.sync.aligned.m16n8k8.row.col.f32.tf32.tf32.f32 "
                 "{%0,%1,%2,%3}, {%4,%5,%6,%7}, {%8,%9}, {%0,%1,%2,%3};"
                 : "+f"(c.x), "+f"(c.y), "+f"(c.z), "+f"(c.w)
                 : "r"(a[0]), "r"(a[1]), "r"(a[2]), "r"(a[3]), "r"(b0), "r"(b1));
}
__device__ __forceinline__ void cp16(void* smem_dst, const void* gsrc) {
    unsigned d = (unsigned)__cvta_generic_to_shared(smem_dst);
    asm volatile("cp.async.cg.shared.global [%0], [%1], 16;" :: "r"(d), "l"(gsrc) : "memory");
}
#define CP_COMMIT() asm volatile("cp.async.commit_group;" ::: "memory")
#define CP_WAIT(N)  asm volatile("cp.async.wait_group %0;" :: "n"(N) : "memory")

__device__ __forceinline__ void st_cs2(float* p, float a, float b) {
    asm volatile("st.global.cs.v2.f32 [%0], {%1,%2};" :: "l"(p), "f"(a), "f"(b) : "memory");
}
__device__ __forceinline__ void st_cs4(float* p, float4 v) {
    asm volatile("st.global.cs.v4.f32 [%0], {%1,%2,%3,%4};"
                 :: "l"(p), "f"(v.x), "f"(v.y), "f"(v.z), "f"(v.w) : "memory");
}

// ---------------- fused: x->bf16 mirror || degree count || Whh transpose ------
__global__ void xbcount_kernel(const float* __restrict__ x, const int* __restrict__ ei,
                               const float* __restrict__ Whh) {
    int bid = blockIdx.x;
    if (bid < 8192) {
        int i = bid * 256 + threadIdx.x;
        float4 v = *(const float4*)(x + (size_t)i * 4);
        __nv_bfloat162 a = __float22bfloat162_rn(make_float2(v.x, v.y));
        __nv_bfloat162 b = __float22bfloat162_rn(make_float2(v.z, v.w));
        uint2 packed = make_uint2(*reinterpret_cast<uint32_t*>(&a), *reinterpret_cast<uint32_t*>(&b));
        *(uint2*)(g_xb + (size_t)i * 4) = packed;
    } else if (bid < 16384) {
        int e = (bid - 8192) * 256 + threadIdx.x;
        atomicAdd(&g_deg[__ldg(&ei[EE + e])], 1);
    } else {
        int idx = (bid - 16384) * 256 + threadIdx.x;   // 65536
        int j = idx >> 7, k = idx & 127;
        g_WT[k * 512 + j] = Whh[idx];
    }
}

// ---------------- fused CSR scan (order-free base via atomic counter) --------
__global__ void csr_scan_kernel() {
    __shared__ int s[256];
    __shared__ int sbase;
    int t = threadIdx.x;
    int i = blockIdx.x * 256 + t;
    int d = g_deg[i];
    s[t] = d;
    __syncthreads();
    for (int off = 1; off < 256; off <<= 1) {
        int u = (t >= off) ? s[t - off] : 0;
        __syncthreads();
        s[t] += u;
        __syncthreads();
    }
    if (t == 255) sbase = atomicAdd(&g_ctr, s[255]);
    __syncthreads();
    int beg = sbase + s[t] - d;
    g_rowptr[i] = beg;
    g_rowend[i] = beg + d;
    g_cursor[i] = beg;
    g_inv[i] = 1.0f / fmaxf((float)d, 1.0f);
    g_deg[i] = 0;
}

__global__ void escatter_kernel(const int* __restrict__ ei) {
    if (blockIdx.x == 0 && threadIdx.x == 0) g_ctr = 0;
    int e = blockIdx.x * 256 + threadIdx.x;
    int src = __ldg(&ei[e]);
    int dst = __ldg(&ei[EE + e]);
    int pos = atomicAdd(&g_cursor[dst], 1);
    g_esrc[pos] = src;
}

// ---------------- aggregation (bf16 gathers via shfl'd byte-offsets) ----------
__global__ void agg1_kernel() {
    int warp = threadIdx.x >> 5, lane = threadIdx.x & 31;
    int n = blockIdx.x * 8 + warp;
    int beg = g_rowptr[n], end = g_rowend[n];
    const char* xb = (const char*)g_xb;
    int lb = lane * 4;
    float2 acc = make_float2(0.0f, 0.0f);
    for (int base = beg; base < end; base += 32) {
        int cnt = end - base; if (cnt > 32) cnt = 32;
        int myoff = (lane < cnt) ? (__ldg(&g_esrc[base + lane]) << 7) : 0;
        int j = 0;
        for (; j + 8 <= cnt; j += 8) {
            uint32_t u[8];
            #pragma unroll
            for (int k = 0; k < 8; k++)
                u[k] = *(const uint32_t*)(xb + __shfl_sync(0xffffffffu, myoff, j + k) + lb);
            #pragma unroll
            for (int k = 0; k < 8; k++) {
                acc.x += __uint_as_float(u[k] << 16);
                acc.y += __uint_as_float(u[k] & 0xFFFF0000u);
            }
        }
        for (; j + 2 <= cnt; j += 2) {
            uint32_t u0 = *(const uint32_t*)(xb + __shfl_sync(0xffffffffu, myoff, j) + lb);
            uint32_t u1 = *(const uint32_t*)(xb + __shfl_sync(0xffffffffu, myoff, j + 1) + lb);
            acc.x += __uint_as_float(u0 << 16) + __uint_as_float(u1 << 16);
            acc.y += __uint_as_float(u0 & 0xFFFF0000u) + __uint_as_float(u1 & 0xFFFF0000u);
        }
        if (j < cnt) {
            uint32_t u0 = *(const uint32_t*)(xb + __shfl_sync(0xffffffffu, myoff, j) + lb);
            acc.x += __uint_as_float(u0 << 16);
            acc.y += __uint_as_float(u0 & 0xFFFF0000u);
        }
    }
    float inv = g_inv[n];
    st_cs2(g_agg1 + (size_t)n * FN + lane * 2, acc.x * inv, acc.y * inv);
}

__global__ void agg2_kernel() {
    int warp = threadIdx.x >> 5, lane = threadIdx.x & 31;
    int n = blockIdx.x * 8 + warp;
    int beg = g_rowptr[n], end = g_rowend[n];
    const char* hb = (const char*)g_h1b;
    int lb = lane * 8;
    float4 acc = make_float4(0.0f, 0.0f, 0.0f, 0.0f);
    for (int base = beg; base < end; base += 32) {
        int cnt = end - base; if (cnt > 32) cnt = 32;
        int myoff = (lane < cnt) ? (__ldg(&g_esrc[base + lane]) << 8) : 0;
        int j = 0;
        for (; j + 4 <= cnt; j += 4) {
            uint2 u[4];
            #pragma unroll
            for (int k = 0; k < 4; k++)
                u[k] = *(const uint2*)(hb + __shfl_sync(0xffffffffu, myoff, j + k) + lb);
            #pragma unroll
            for (int k = 0; k < 4; k++) {
                acc.x += __uint_as_float(u[k].x << 16);
                acc.y += __uint_as_float(u[k].x & 0xFFFF0000u);
                acc.z += __uint_as_float(u[k].y << 16);
                acc.w += __uint_as_float(u[k].y & 0xFFFF0000u);
            }
        }
        for (; j < cnt; j++) {
            uint2 u0 = *(const uint2*)(hb + __shfl_sync(0xffffffffu, myoff, j) + lb);
            acc.x += __uint_as_float(u0.x << 16);
            acc.y += __uint_as_float(u0.x & 0xFFFF0000u);
            acc.z += __uint_as_float(u0.y << 16);
            acc.w += __uint_as_float(u0.y & 0xFFFF0000u);
        }
    }
    float inv = g_inv[n];
    acc.x *= inv; acc.y *= inv; acc.z *= inv; acc.w *= inv;
    st_cs4(g_agg2 + (size_t)n * HH + lane * 4, acc);
}

// ============= tf32 mma GEMMs, cp.async double-buffered A ====================
// gemm1: 128x128 tile, K=128 ([agg1|x]); epilogue -> bf16 h1b ONLY, coalesced
// via smem restaging in the consumed A buffer.
__global__ void __launch_bounds__(256, 1)
mmagemm1_kernel(const float* __restrict__ x, const float* __restrict__ Wl,
                const float* __restrict__ Wr, const float* __restrict__ b1) {
    extern __shared__ char smem[];
    uint32_t* sBf = (uint32_t*)smem;                       // 64KB
    uint32_t* sA0 = (uint32_t*)(smem + 65536);             // 67584B
    uint32_t* sA1 = (uint32_t*)(smem + 65536 + 67584);
    float*    sBias = (float*)(smem + 65536 + 2 * 67584);
    int t = threadIdx.x;
    int wid = t >> 5, lane = t & 31;
    int g = lane >> 2, c = lane & 3;
    int wm = wid >> 1, wn = wid & 1;
    int r0 = wm * 32, jbase = wn * 64;

    for (int i = t; i < 16 * 16 * 32; i += 256) {
        int lane_i = i & 31, nt = (i >> 5) & 15, ks = i >> 9;
        int j = nt * 8 + (lane_i >> 2);
        int k = ks * 8 + (lane_i & 3);
        const float* Wp0 = (k < 64) ? &Wl[j * 64 + k] : &Wr[j * 64 + k - 64];
        const float* Wp1 = (k + 4 < 64) ? &Wl[j * 64 + k + 4] : &Wr[j * 64 + k + 4 - 64];
        sBf[i * 2 + 0] = cvt_tf32(__ldg(Wp0));
        sBf[i * 2 + 1] = cvt_tf32(__ldg(Wp1));
    }
    if (t < 128) sBias[t] = __ldg(&b1[t]);
    __syncthreads();

    const int T = NN / 128, G = gridDim.x;
    auto issueA = [&](int tile, uint32_t* buf) {
        int row0 = tile * 128;
        #pragma unroll
        for (int i = 0; i < 16; i++) {
            int idx = t + i * 256;
            int r = idx >> 5, q = idx & 31;
            const float* src = (q < 16) ? (g_agg1 + (size_t)(row0 + r) * FN + q * 4)
                                        : (x + (size_t)(row0 + r) * FN + (q - 16) * 4);
            cp16(buf + r * 132 + q * 4, src);
        }
        CP_COMMIT();
    };

    int tile = blockIdx.x;
    if (tile < T) issueA(tile, sA0);
    int cur = 0;
    while (tile < T) {
        int nxt = tile + G;
        uint32_t* bufc = cur ? sA1 : sA0;
        uint32_t* bufn = cur ? sA0 : sA1;
        if (nxt < T) { issueA(nxt, bufn); CP_WAIT(1); } else { CP_WAIT(0); }
        __syncthreads();

        float4 acc[2][8];
        #pragma unroll
        for (int mt = 0; mt < 2; mt++)
            #pragma unroll
            for (int nt = 0; nt < 8; nt++) acc[mt][nt] = make_float4(0.f, 0.f, 0.f, 0.f);

        #pragma unroll
        for (int ks = 0; ks < 16; ks++) {
            int k0 = ks * 8;
            uint32_t a[2][4];
            #pragma unroll
            for (int mt = 0; mt < 2; mt++) {
                const uint32_t* base = bufc + (r0 + mt * 16 + g) * 132 + k0 + c;
                a[mt][0] = base[0];
                a[mt][1] = base[8 * 132];
                a[mt][2] = base[4];
                a[mt][3] = base[8 * 132 + 4];
            }
            const uint32_t* bb = sBf + ((ks * 16 + wn * 8) * 32 + lane) * 2;
            #pragma unroll
            for (int nt = 0; nt < 8; nt++) {
                uint32_t b0 = bb[nt * 64], b1 = bb[nt * 64 + 1];
                mma_tf32(acc[0][nt], a[0], b0, b1);
                mma_tf32(acc[1][nt], a[1], b0, b1);
            }
        }

        // epilogue: bias+ReLU -> bf16, restage in bufc (consumed), coalesced STG
        __syncthreads();
        #pragma unroll
        for (int mt = 0; mt < 2; mt++) {
            int rloc = r0 + mt * 16 + g;
            #pragma unroll
            for (int nt = 0; nt < 8; nt++) {
                int j = jbase + nt * 8 + 2 * c;
                int w = (jbase + nt * 8) / 2 + c;
                float bx = sBias[j], by = sBias[j + 1];
                float4 ac = acc[mt][nt];
                __nv_bfloat162 lo = __float22bfloat162_rn(
                    make_float2(fmaxf(ac.x + bx, 0.f), fmaxf(ac.y + by, 0.f)));
                __nv_bfloat162 hi = __float22bfloat162_rn(
                    make_float2(fmaxf(ac.z + bx, 0.f), fmaxf(ac.w + by, 0.f)));
                bufc[rloc * 132 + w]       = *reinterpret_cast<uint32_t*>(&lo);
                bufc[(rloc + 8) * 132 + w] = *reinterpret_cast<uint32_t*>(&hi);
            }
        }
        __syncthreads();
        int row0 = tile * 128;
        #pragma unroll
        for (int p = 0; p < 8; p++) {
            int idx = t + p * 256;             // 2048 = 128 rows x 16 quads
            int r = idx >> 4, q = idx & 15;
            uint4 v = make_uint4(bufc[r * 132 + q * 4 + 0], bufc[r * 132 + q * 4 + 1],
                                 bufc[r * 132 + q * 4 + 2], bufc[r * 132 + q * 4 + 3]);
            *(uint4*)(g_h1b + (size_t)(row0 + r) * HH + q * 8) = v;
        }
        __syncthreads();
        cur ^= 1;
        tile = nxt;
    }
}

// gemm2: 64x128 tile, K=256: kh=0 stages fp32 agg2, kh=1 stages bf16 h1b
// (unpacked to tf32 in the fragment loads).
__global__ void __launch_bounds__(256, 1)
mmagemm2_kernel(const float* __restrict__ Wl, const float* __restrict__ Wr,
                const float* __restrict__ b2) {
    extern __shared__ char smem[];
    uint32_t* sBf = (uint32_t*)smem;                         // 128KB
    uint32_t* sA0 = (uint32_t*)(smem + 131072);              // 33792B
    uint32_t* sA1 = (uint32_t*)(smem + 131072 + 33792);
    float*    sBias = (float*)(smem + 131072 + 2 * 33792);
    int t = threadIdx.x;
    int wid = t >> 5, lane = t & 31;
    int g = lane >> 2, c = lane & 3;
    int wm = wid >> 1, wn = wid & 1;
    int r0 = wm * 16, jbase = wn * 64;

    for (int i = t; i < 32 * 16 * 32; i += 256) {
        int lane_i = i & 31, nt = (i >> 5) & 15, ks = i >> 9;
        int j = nt * 8 + (lane_i >> 2);
        int k = ks * 8 + (lane_i & 3);
        const float* Wp0 = (k < 128) ? &Wl[j * 128 + k] : &Wr[j * 128 + k - 128];
        const float* Wp1 = (k + 4 < 128) ? &Wl[j * 128 + k + 4] : &Wr[j * 128 + k + 4 - 128];
        sBf[i * 2 + 0] = cvt_tf32(__ldg(Wp0));
        sBf[i * 2 + 1] = cvt_tf32(__ldg(Wp1));
    }
    if (t < 128) sBias[t] = __ldg(&b2[t]);
    __syncthreads();

    const int T = NN / 64, G = gridDim.x;
    auto issueA = [&](int tile, int kh, uint32_t* buf) {
        int row0 = tile * 64;
        if (kh == 0) {
            #pragma unroll
            for (int i = 0; i < 8; i++) {
                int idx = t + i * 256;
                int r = idx >> 5, q = idx & 31;
                cp16(buf + r * 132 + q * 4, g_agg2 + (size_t)(row0 + r) * HH + q * 4);
            }
        } else {
            #pragma unroll
            for (int i = 0; i < 4; i++) {
                int idx = t + i * 256;            // 1024 = 64 rows x 16 chunks
                int r = idx >> 4, q = idx & 15;
                cp16(buf + r * 68 + q * 4, g_h1b + (size_t)(row0 + r) * HH + q * 8);
            }
        }
        CP_COMMIT();
    };

    int tile = blockIdx.x;
    if (tile < T) issueA(tile, 0, sA0);
    int cur = 0;
    while (tile < T) {
        float4 acc[8];
        #pragma unroll
        for (int nt = 0; nt < 8; nt++) acc[nt] = make_float4(0.f, 0.f, 0.f, 0.f);

        #pragma unroll 1
        for (int kh = 0; kh < 2; kh++) {
            uint32_t* bufc = cur ? sA1 : sA0;
            uint32_t* bufn = cur ? sA0 : sA1;
            int ntile = tile, nkh = kh + 1;
            if (nkh == 2) { ntile = tile + G; nkh = 0; }
            if (ntile < T) { issueA(ntile, nkh, bufn); CP_WAIT(1); } else { CP_WAIT(0); }
            __syncthreads();

            if (kh == 0) {
                #pragma unroll
                for (int ks = 0; ks < 16; ks++) {
                    int k0 = ks * 8;
                    uint32_t a[4];
                    const uint32_t* base = bufc + (r0 + g) * 132 + k0 + c;
                    a[0] = base[0];
                    a[1] = base[8 * 132];
                    a[2] = base[4];
                    a[3] = base[8 * 132 + 4];
                    const uint32_t* bb = sBf + ((ks * 16 + wn * 8) * 32 + lane) * 2;
                    #pragma unroll
                    for (int nt = 0; nt < 8; nt++)
                        mma_tf32(acc[nt], a, bb[nt * 64], bb[nt * 64 + 1]);
                }
            } else {
                int hi = c & 1;
                int wbase = c >> 1;
                #pragma unroll
                for (int ks = 0; ks < 16; ks++) {
                    int w0 = ks * 4 + wbase;       // (ks*8)/2 + (c>>1)
                    uint32_t a[4];
                    const uint32_t* baseb = bufc + (r0 + g) * 68;
                    uint32_t A0 = baseb[w0],          B0 = baseb[w0 + 2];
                    uint32_t A1 = baseb[8 * 68 + w0], B1 = baseb[8 * 68 + w0 + 2];
                    a[0] = hi ? (A0 & 0xFFFF0000u) : (A0 << 16);
                    a[1] = hi ? (A1 & 0xFFFF0000u) : (A1 << 16);
                    a[2] = hi ? (B0 & 0xFFFF0000u) : (B0 << 16);
                    a[3] = hi ? (B1 & 0xFFFF0000u) : (B1 << 16);
                    const uint32_t* bb = sBf + (((16 + ks) * 16 + wn * 8) * 32 + lane) * 2;
                    #pragma unroll
                    for (int nt = 0; nt < 8; nt++)
                        mma_tf32(acc[nt], a, bb[nt * 64], bb[nt * 64 + 1]);
                }
            }
            __syncthreads();
            cur ^= 1;
        }

        int m0 = tile * 64 + r0 + g;
        #pragma unroll
        for (int nt = 0; nt < 8; nt++) {
            int j = jbase + nt * 8 + 2 * c;
            float bx = sBias[j], by = sBias[j + 1];
            float4 ac = acc[nt];
            *(float2*)(g_nemb + (size_t)m0 * HH + j) =
                make_float2(fmaxf(ac.x + bx, 0.f), fmaxf(ac.y + by, 0.f));
            *(float2*)(g_nemb + (size_t)(m0 + 8) * HH + j) =
                make_float2(fmaxf(ac.z + bx, 0.f), fmaxf(ac.w + by, 0.f));
        }
        tile += G;
    }
}

// ---------------- graph mean pooling -------------------------------------------
__global__ void pool_kernel(const int* __restrict__ batch) {
    int t = threadIdx.x;
    int j = t & 127, half = t >> 7;
    int n0 = blockIdx.x * 256 + half * 128;
    float sum = 0.0f, cc = 0.0f;
    int cur = __ldg(&batch[n0]);
    for (int r = 0; r < 128; r++) {
        int b = __ldg(&batch[n0 + r]);
        if (b != cur) {
            atomicAdd(&g_gsum[cur * HH + j], sum);
            if (j == 0) atomicAdd(&g_gcnt[cur], cc);
            sum = 0.0f; cc = 0.0f; cur = b;
        }
        sum += g_nemb[(size_t)(n0 + r) * HH + j];
        cc += 1.0f;
    }
    atomicAdd(&g_gsum[cur * HH + j], sum);
    if (j == 0) atomicAdd(&g_gcnt[cur], cc);
}

// ---------------- xg GEMM on tensor cores (cp.async staging) ------------------
__global__ void __launch_bounds__(256, 1)
xg_mma_kernel(const int* __restrict__ path_idx, const float* __restrict__ Wih,
              const float* __restrict__ bih, const float* __restrict__ bhh) {
    extern __shared__ char smem[];
    uint32_t* sBf = (uint32_t*)smem;
    uint32_t* sA  = (uint32_t*)(smem + 65536);
    float*    sBias = (float*)(smem + 65536 + 67584);
    __shared__ int snode[128];
    int t = threadIdx.x;
    int wid = t >> 5, lane = t & 31;
    int g = lane >> 2, c = lane & 3;
    int wm = wid >> 1, wn = wid & 1;
    int r0 = wm * 32;
    int jchunk = blockIdx.y * 128;
    int row0 = blockIdx.x * 128;

    if (t < 128) snode[t] = __ldg(&path_idx[row0 + t]);
    for (int i = t; i < 16 * 16 * 32; i += 256) {
        int lane_i = i & 31, nt = (i >> 5) & 15, ks = i >> 9;
        int j = nt * 8 + (lane_i >> 2);
        int k = ks * 8 + (lane_i & 3);
        sBf[i * 2 + 0] = cvt_tf32(__ldg(&Wih[(size_t)(jchunk + j) * 128 + k]));
        sBf[i * 2 + 1] = cvt_tf32(__ldg(&Wih[(size_t)(jchunk + j) * 128 + k + 4]));
    }
    if (t < 128) sBias[t] = __ldg(&bih[jchunk + t]) + __ldg(&bhh[jchunk + t]);
    __syncthreads();

    #pragma unroll
    for (int i = 0; i < 16; i++) {
        int idx = t + i * 256;
        int r = idx >> 5, q = idx & 31;
        cp16(sA + r * 132 + q * 4, g_nemb + (size_t)snode[r] * HH + q * 4);
    }
    CP_COMMIT();
    CP_WAIT(0);
    __syncthreads();

    float4 acc[2][8];
    #pragma unroll
    for (int mt = 0; mt < 2; mt++)
        #pragma unroll
        for (int nt = 0; nt < 8; nt++) acc[mt][nt] = make_float4(0.f, 0.f, 0.f, 0.f);

    #pragma unroll
    for (int ks = 0; ks < 16; ks++) {
        int k0 = ks * 8;
        uint32_t a[2][4];
        #pragma unroll
        for (int mt = 0; mt < 2; mt++) {
            const uint32_t* base = sA + (r0 + mt * 16 + g) * 132 + k0 + c;
            a[mt][0] = base[0];
            a[mt][1] = base[8 * 132];
            a[mt][2] = base[4];
            a[mt][3] = base[8 * 132 + 4];
        }
        const uint32_t* bb = sBf + ((ks * 16 + wn * 8) * 32 + lane) * 2;
        #pragma unroll
        for (int nt = 0; nt < 8; nt++) {
            uint32_t b0 = bb[nt * 64], b1 = bb[nt * 64 + 1];
            mma_tf32(acc[0][nt], a[0], b0, b1);
            mma_tf32(acc[1][nt], a[1], b0, b1);
        }
    }

    #pragma unroll
    for (int mt = 0; mt < 2; mt++) {
        int m0 = row0 + r0 + mt * 16 + g;
        #pragma unroll
        for (int nt = 0; nt < 8; nt++) {
            int jl = wn * 64 + nt * 8 + 2 * c;
            float bx = sBias[jl], by = sBias[jl + 1];
            float4 ac = acc[mt][nt];
            *(float2*)(g_Xg + (size_t)m0 * 512 + jchunk + jl) = make_float2(ac.x + bx, ac.y + by);
            *(float2*)(g_Xg + (size_t)(m0 + 8) * 512 + jchunk + jl) = make_float2(ac.z + bx, ac.w + by);
        }
    }
}

// ---------------- LSTM + fused scoring head -----------------------------------
#define LSTM_WROWS 96
__global__ void lstm_kernel(const int* __restrict__ path_len,
                            const float* __restrict__ flow, const float* __restrict__ Wf,
                            const float* __restrict__ bf, const float* __restrict__ Ws1,
                            const float* __restrict__ bs1, const float* __restrict__ Ws2,
                            const float* __restrict__ bs2, float* __restrict__ out) {
    extern __shared__ float dyn[];
    float* sW  = dyn;
    float* sh  = dyn + LSTM_WROWS * 512;
    float* scm = sh + 256;
    float* sG  = scm + 256;              // 1024 floats, reused by head
    __shared__ int splen[2];
    int t = threadIdx.x;
    int b0 = blockIdx.x * 2;
    for (int i = t; i < LSTM_WROWS * 512 / 4; i += 128)
        *(float4*)(sW + i * 4) = *(const float4*)(g_WT + i * 4);
    for (int i = t; i < 256; i += 128) { sh[i] = 0.0f; scm[i] = 0.0f; }
    if (t < 2) splen[t] = path_len[b0 + t];
    __syncthreads();
    int jq = t;
    for (int step = 0; step < LL; step++) {
        float4 a0 = *(const float4*)(g_Xg + ((size_t)b0 * LL + step) * 512 + jq * 4);
        float4 a1 = *(const float4*)(g_Xg + ((size_t)(b0 + 1) * LL + step) * 512 + jq * 4);
        #pragma unroll 4
        for (int k = 0; k < LSTM_WROWS; k++) {
            float4 w = *(const float4*)(sW + k * 512 + jq * 4);
            float hA = sh[k], hB = sh[128 + k];
            a0.x += w.x * hA; a0.y += w.y * hA; a0.z += w.z * hA; a0.w += w.w * hA;
            a1.x += w.x * hB; a1.y += w.y * hB; a1.z += w.z * hB; a1.w += w.w * hB;
        }
        #pragma unroll 4
        for (int k = LSTM_WROWS; k < 128; k++) {
            float4 w = *(const float4*)(g_WT + k * 512 + jq * 4);
            float hA = sh[k], hB = sh[128 + k];
            a0.x += w.x * hA; a0.y += w.y * hA; a0.z += w.z * hA; a0.w += w.w * hA;
            a1.x += w.x * hB; a1.y += w.y * hB; a1.z += w.z * hB; a1.w += w.w * hB;
        }
        *(float4*)(sG + jq * 4) = a0;
        *(float4*)(sG + 512 + jq * 4) = a1;
        __syncthreads();
        #pragma unroll
        for (int u = 0; u < 2; u++) {
            int idx = t + u * 128;
            int b = idx >> 7, j = idx & 127;
            float ig = sG[b * 512 + j];
            float fg = sG[b * 512 + 128 + j];
            float gg = sG[b * 512 + 256 + j];
            float og = sG[b * 512 + 384 + j];
            float cn = sigf(fg) * scm[b * 128 + j] + sigf(ig) * tanhf(gg);
            float hn = sigf(og) * tanhf(cn);
            if (step < splen[b]) { scm[b * 128 + j] = cn; sh[b * 128 + j] = hn; }
        }
        __syncthreads();
    }

    float* comb = sG;
    float* red_ = sG + 384;
    int j = t;
    #pragma unroll 1
    for (int bl = 0; bl < 2; bl++) {
        int b = b0 + bl;
        comb[j] = g_gsum[b * HH + j] * (1.0f / fmaxf(g_gcnt[b], 1.0f));
        comb[128 + j] = sh[bl * 128 + j];
        if (j < 64) {
            float a = __ldg(&bf[j]);
            #pragma unroll
            for (int k = 0; k < FF; k++) a += flow[b * FF + k] * Wf[j * FF + k];
            comb[256 + j] = fmaxf(a, 0.0f);
        }
        __syncthreads();
        g_gsum[b * HH + j] = 0.0f;
        if (j == 0) g_gcnt[b] = 0.0f;

        float acc = __ldg(&bs1[j]);
        const float4* wr = (const float4*)(Ws1 + (size_t)j * 320);
        const float4* cb = (const float4*)comb;
        #pragma unroll 8
        for (int k = 0; k < 80; k++) {
            float4 w = wr[k], c = cb[k];
            acc += w.x * c.x + w.y * c.y + w.z * c.z + w.w * c.w;
        }
        float h = fmaxf(acc, 0.0f);
        red_[j] = h * __ldg(&Ws2[j]);
        __syncthreads();
        for (int s = 64; s > 0; s >>= 1) {
            if (j < s) red_[j] += red_[j + s];
            __syncthreads();
        }
        if (j == 0) out[b] = red_[0] + __ldg(&bs2[0]);
        __syncthreads();
    }
}

// ---------------- launch ------------------------------------------------------
extern "C" void kernel_launch(void* const* d_in, const int* in_sizes, int n_in,
                              void* d_out, int out_size) {
    const float* x        = (const float*)d_in[0];
    const int*   ei       = (const int*)d_in[1];
    const int*   batch    = (const int*)d_in[2];
    const int*   path_idx = (const int*)d_in[3];
    const int*   path_len = (const int*)d_in[4];
    const float* flow     = (const float*)d_in[5];
    const float* Wl1 = (const float*)d_in[6];
    const float* Wr1 = (const float*)d_in[7];
    const float* b1  = (const float*)d_in[8];
    const float* Wl2 = (const float*)d_in[9];
    const float* Wr2 = (const float*)d_in[10];
    const float* b2  = (const float*)d_in[11];
    const float* Wih = (const float*)d_in[12];
    const float* Whh = (const float*)d_in[13];
    const float* bih = (const float*)d_in[14];
    const float* bhh = (const float*)d_in[15];
    const float* Wf  = (const float*)d_in[16];
    const float* bf  = (const float*)d_in[17];
    const float* Ws1 = (const float*)d_in[18];
    const float* bs1 = (const float*)d_in[19];
    const float* Ws2 = (const float*)d_in[20];
    const float* bs2 = (const float*)d_in[21];
    float* out = (float*)d_out;

    const int SMG1 = 65536 + 2 * 67584 + 512;     // 201280
    const int SMG2 = 131072 + 2 * 33792 + 512;    // 199168
    const int SMXG = 65536 + 67584 + 512;         // 133632
    const int SMLSTM = (LSTM_WROWS * 512 + 256 + 256 + 1024) * 4;   // 202752
    cudaFuncSetAttribute(mmagemm1_kernel, cudaFuncAttributeMaxDynamicSharedMemorySize, SMG1);
    cudaFuncSetAttribute(mmagemm2_kernel, cudaFuncAttributeMaxDynamicSharedMemorySize, SMG2);
    cudaFuncSetAttribute(xg_mma_kernel,   cudaFuncAttributeMaxDynamicSharedMemorySize, SMXG);
    cudaFuncSetAttribute(lstm_kernel,     cudaFuncAttributeMaxDynamicSharedMemorySize, SMLSTM);

    xbcount_kernel<<<16640, 256>>>(x, ei, Whh);
    csr_scan_kernel<<<512, 256>>>();
    escatter_kernel<<<8192, 256>>>(ei);
    agg1_kernel<<<16384, 256>>>();
    mmagemm1_kernel<<<148, 256, SMG1>>>(x, Wl1, Wr1, b1);
    agg2_kernel<<<16384, 256>>>();
    mmagemm2_kernel<<<148, 256, SMG2>>>(Wl2, Wr2, b2);
    pool_kernel<<<512, 256>>>(batch);
    xg_mma_kernel<<<dim3(64, 4), 256, SMXG>>>(path_idx, Wih, bih, bhh);
    lstm_kernel<<<128, 128, SMLSTM>>>(path_len, flow, Wf, bf, Ws1, bs1, Ws2, bs2, out);
}